// round 9
// baseline (speedup 1.0000x reference)
#include <cuda_runtime.h>
#include <cuda_fp16.h>
#include <cstdint>
#include <cfloat>
#include <math_constants.h>

#define Bev 128
#define Pn  200
#define Kn  60
#define Hd  64
#define Nn  (Bev*Pn)          // 25600
#define En  (Nn*Kn)           // 1,536,000

// ---------------- scratch (no cudaMalloc allowed) ----------------
__device__ __align__(16) float g_u[Nn*Hd];   // u = x@W1[:4] + pos@W1[4:] + b1
__device__ __align__(16) float g_v[Nn*Hd];   // v = pos@W1[4:]
__device__ int   g_nbr[En];                  // sorted knn neighbor ids

// ================= helpers =========================================
__device__ __forceinline__ uint32_t smem_u32(const void* p) {
    uint32_t a;
    asm("{ .reg .u64 t; cvta.to.shared.u64 t, %1; cvt.u32.u64 %0, t; }" : "=r"(a) : "l"(p));
    return a;
}
__device__ __forceinline__ void ldsm4(uint32_t* r, uint32_t addr) {
    asm volatile("ldmatrix.sync.aligned.m8n8.x4.shared.b16 {%0,%1,%2,%3}, [%4];"
        : "=r"(r[0]), "=r"(r[1]), "=r"(r[2]), "=r"(r[3]) : "r"(addr));
}
__device__ __forceinline__ void mma16816(float* d, const uint32_t* a, const uint32_t* b) {
    asm volatile("mma.sync.aligned.m16n8k16.row.col.f32.f16.f16.f32 "
        "{%0,%1,%2,%3}, {%4,%5,%6,%7}, {%8,%9}, {%0,%1,%2,%3};"
        : "+f"(d[0]), "+f"(d[1]), "+f"(d[2]), "+f"(d[3])
        : "r"(a[0]), "r"(a[1]), "r"(a[2]), "r"(a[3]), "r"(b[0]), "r"(b[1]));
}
__device__ __forceinline__ uint32_t pkh2(__half a, __half b) {
    __half2 t = __halves2half2(a, b);
    return *reinterpret_cast<uint32_t*>(&t);
}
__device__ __forceinline__ void cpa16(uint32_t dst, const void* src) {
    asm volatile("cp.async.cg.shared.global [%0], [%1], 16;" :: "r"(dst), "l"(src));
}

// ------- kernel 1: fused uv precompute + warp-per-target exact knn -------
// 25 blocks/event, 8 warps/block, one warp per target. Each lane owns 7
// candidates as u64 keys (d2bits<<32 | j); 60 extraction rounds via
// REDUX.MIN (d2 bits, then j among achievers) == stable (d2 asc, j asc),
// identical tie semantics to lax.top_k. d2 formula bit-identical to prior
// passing kernels.
__global__ void __launch_bounds__(256, 1)
knn_kernel(const float* __restrict__ pos, const float* __restrict__ x,
           const float* __restrict__ W1, const float* __restrict__ b1,
           float* __restrict__ out,
           int write_aux, long long off_pos, long long off_batch, long long off_edge) {
    __shared__ float spx[Pn], spy[Pn], spz[Pn];
    int blk = blockIdx.x;              // 0..3199
    int b   = blk / 25;                // event
    int sub = blk % 25;                // 8-target group within event
    int tid = threadIdx.x, lane = tid & 31, warp = tid >> 5;

    for (int t = tid; t < Pn; t += 256) {
        spx[t] = pos[(b*Pn+t)*3+0];
        spy[t] = pos[(b*Pn+t)*3+1];
        spz[t] = pos[(b*Pn+t)*3+2];
    }
    __syncthreads();

    // ---- uv for this block's 8 nodes (512 outputs, 2 per thread) ----
    for (int e = tid; e < 8*64; e += 256) {
        int nl = e >> 6, c = e & 63;
        int n  = sub*8 + nl;
        int gn = b*Pn + n;
        float4 xv = *(const float4*)(x + (size_t)gn*4);
        float a = b1[c];
        a = fmaf(xv.x, W1[0*64+c], a);
        a = fmaf(xv.y, W1[1*64+c], a);
        a = fmaf(xv.z, W1[2*64+c], a);
        a = fmaf(xv.w, W1[3*64+c], a);
        float vv = spx[n] * W1[4*64+c];
        vv = fmaf(spy[n], W1[5*64+c], vv);
        vv = fmaf(spz[n], W1[6*64+c], vv);
        g_u[(size_t)gn*64 + c] = a + vv;
        g_v[(size_t)gn*64 + c] = vv;
    }

    // ---- knn: one warp per target ----
    int i  = sub*8 + warp;
    int gi = b*Pn + i;
    float pix = spx[i], piy = spy[i], piz = spz[i];

    unsigned long long key[7];
#pragma unroll
    for (int k = 0; k < 7; k++) {
        int j  = lane + 32*k;
        int js = (j < Pn) ? j : 0;
        float dx = spx[js]-pix, dy = spy[js]-piy, dz = spz[js]-piz;
        float d2 = dx*dx; d2 = fmaf(dy,dy,d2); d2 = fmaf(dz,dz,d2);
        bool valid = (j < Pn) && (j != i);
        key[k] = valid ? (((unsigned long long)__float_as_uint(d2) << 32) | (unsigned)j)
                       : ~0ull;
    }
    unsigned long long lm = key[0];
#pragma unroll
    for (int k = 1; k < 7; k++) lm = (key[k] < lm) ? key[k] : lm;

    for (int t = 0; t < Kn; t++) {
        unsigned hi   = (unsigned)(lm >> 32);
        unsigned rmin = __reduce_min_sync(0xffffffffu, hi);
        unsigned cand = (hi == rmin) ? (unsigned)lm : 0xffffffffu;
        unsigned j    = __reduce_min_sync(0xffffffffu, cand);

        if (lane == 0) {
            g_nbr[(size_t)gi*Kn + t] = b*Pn + (int)j;
            if (write_aux) {
                out[off_edge +      (long long)gi*Kn + t] = (float)(b*Pn + (int)j);
                out[off_edge + En + (long long)gi*Kn + t] = (float)gi;
            }
        }
        if (lane == (int)(j & 31)) {
            int kk = (int)(j >> 5);
#pragma unroll
            for (int k2 = 0; k2 < 7; k2++) if (k2 == kk) key[k2] = ~0ull;
            lm = key[0];
#pragma unroll
            for (int k2 = 1; k2 < 7; k2++) lm = (key[k2] < lm) ? key[k2] : lm;
        }
    }

    if (lane == 0 && write_aux) {
        out[off_pos + (long long)gi*3+0] = pix;
        out[off_pos + (long long)gi*3+1] = piy;
        out[off_pos + (long long)gi*3+2] = piz;
        out[off_batch + gi] = (float)b;
    }
}

// ---------------- kernel 2: HMMA mlp + fused max-aggregate --------
// (byte-exact round-8 version — known good at 171.5us)
__global__ void __launch_bounds__(128)
mlp3_kernel(const float* __restrict__ W2, const float* __restrict__ b2,
            float* __restrict__ out) {
    __shared__ __align__(16) __half sW[2][64][72];    // [hi/lo][ch][k]
    __shared__ __align__(16) float  sU[4][2][8][72];  // [warp][stage][row][64+pad]
    int tid = threadIdx.x, lane = tid & 31, warp = tid >> 5;

    for (int e = tid; e < 64*64; e += 128) {
        int k = e >> 6, ch = e & 63;
        float w = W2[k*64 + ch];
        __half hi = __float2half_rn(w);
        __half lo = __float2half_rn(w - __half2float(hi));
        sW[0][ch][k] = hi;
        sW[1][ch][k] = lo;
    }
    __syncthreads();

    // A fragments (held in regs for the whole kernel)
    uint32_t aH[4][4][4], aL[4][4][4];
    {
        int r = (lane & 7) + ((lane >> 3) & 1) * 8;
        int c = ((lane >> 4) & 1) * 8;
#pragma unroll
        for (int mt = 0; mt < 4; mt++)
#pragma unroll
            for (int kt = 0; kt < 4; kt++) {
                ldsm4(aH[mt][kt], smem_u32(&sW[0][mt*16 + r][kt*16 + c]));
                ldsm4(aL[mt][kt], smem_u32(&sW[1][mt*16 + r][kt*16 + c]));
            }
    }

    int i = blockIdx.x * 4 + warp;                    // node id
    const int cb = (lane & 3) * 2;                    // k base within k-tile
    const int mrow = lane >> 2;                       // message row in group
    const int seg  = lane & 15;                       // 16B chunk within row
    const int hi4  = lane >> 4;                       // row parity for prefetch

    // all 60 neighbor ids in 2 regs, distributed by shfl
    int nA = g_nbr[(size_t)i*Kn + lane];
    int nB = (lane < Kn - 32) ? g_nbr[(size_t)i*Kn + 32 + lane] : 0;

    const uint32_t suBase = smem_u32(&sU[warp][0][0][0]);   // stage stride 2304B

    float2 vA[4], vB[4];
#pragma unroll
    for (int kt = 0; kt < 4; kt++) {
        vA[kt] = *(const float2*)(g_v + (size_t)i*64 + kt*16 + cb);
        vB[kt] = *(const float2*)(g_v + (size_t)i*64 + kt*16 + cb + 8);
    }

    float rm0[4], rm1[4];
#pragma unroll
    for (int mt = 0; mt < 4; mt++) { rm0[mt] = -FLT_MAX; rm1[mt] = -FLT_MAX; }

#define PREFETCH_GRP(gg, st) do {                                            \
        _Pragma("unroll")                                                    \
        for (int it = 0; it < 4; it++) {                                     \
            int rr = 2*it + hi4;                                             \
            int mm = (gg)*8 + rr;                                            \
            int jj = (mm < 32) ? __shfl_sync(0xffffffffu, nA, mm)            \
                   : (mm < Kn) ? __shfl_sync(0xffffffffu, nB, mm - 32)       \
                   : i;                                                      \
            cpa16(suBase + (st)*2304 + rr*288 + seg*16,                      \
                  (const char*)g_u + (size_t)jj*256 + seg*16);               \
        }                                                                    \
        asm volatile("cp.async.commit_group;" ::: "memory");                 \
    } while (0)

    PREFETCH_GRP(0, 0);

    for (int g = 0; g < 8; g++) {                     // 8 groups of 8 messages
        if (g < 7) {
            PREFETCH_GRP(g+1, (g+1)&1);
            asm volatile("cp.async.wait_group 1;" ::: "memory");
        } else {
            asm volatile("cp.async.wait_group 0;" ::: "memory");
        }
        __syncwarp();

        const float* su = &sU[warp][g & 1][0][0];
        uint32_t bH[4][2], bL[4][2];
#pragma unroll
        for (int kt = 0; kt < 4; kt++) {
            float2 uA = *(const float2*)(su + mrow*72 + kt*16 + cb);
            float2 uB = *(const float2*)(su + mrow*72 + kt*16 + cb + 8);
            float h0 = fmaxf(uA.x - vA[kt].x, 0.f);
            float h1 = fmaxf(uA.y - vA[kt].y, 0.f);
            float h2 = fmaxf(uB.x - vB[kt].x, 0.f);
            float h3 = fmaxf(uB.y - vB[kt].y, 0.f);
            __half q0 = __float2half_rn(h0), q1 = __float2half_rn(h1);
            __half q2 = __float2half_rn(h2), q3 = __float2half_rn(h3);
            bH[kt][0] = pkh2(q0, q1);
            bH[kt][1] = pkh2(q2, q3);
            bL[kt][0] = pkh2(__float2half_rn(h0 - __half2float(q0)),
                             __float2half_rn(h1 - __half2float(q1)));
            bL[kt][1] = pkh2(__float2half_rn(h2 - __half2float(q2)),
                             __float2half_rn(h3 - __half2float(q3)));
        }

#pragma unroll
        for (int mt = 0; mt < 4; mt++) {
            float dh[4] = {0,0,0,0}, dl[4] = {0,0,0,0}, da[4] = {0,0,0,0};
#pragma unroll
            for (int kt = 0; kt < 4; kt++) {
                mma16816(dh, aH[mt][kt], bH[kt]);
                mma16816(dl, aH[mt][kt], bL[kt]);
                mma16816(da, aL[mt][kt], bH[kt]);
            }
            float d0 = dh[0] + dl[0] + da[0];
            float d1 = dh[1] + dl[1] + da[1];
            float d2 = dh[2] + dl[2] + da[2];
            float d3 = dh[3] + dl[3] + da[3];
            rm0[mt] = fmaxf(rm0[mt], fmaxf(d0, d1));
            rm1[mt] = fmaxf(rm1[mt], fmaxf(d2, d3));
        }
        __syncwarp();   // reads of this stage done before next prefetch lands
    }

#pragma unroll
    for (int mt = 0; mt < 4; mt++) {
        rm0[mt] = fmaxf(rm0[mt], __shfl_xor_sync(0xffffffffu, rm0[mt], 1));
        rm0[mt] = fmaxf(rm0[mt], __shfl_xor_sync(0xffffffffu, rm0[mt], 2));
        rm1[mt] = fmaxf(rm1[mt], __shfl_xor_sync(0xffffffffu, rm1[mt], 1));
        rm1[mt] = fmaxf(rm1[mt], __shfl_xor_sync(0xffffffffu, rm1[mt], 2));
    }
    if ((lane & 3) == 0) {
        int r = lane >> 2;
#pragma unroll
        for (int mt = 0; mt < 4; mt++) {
            int ch = mt*16 + r;
            out[(size_t)i*64 + ch]     = fmaxf(rm0[mt] + b2[ch],     0.f);
            out[(size_t)i*64 + ch + 8] = fmaxf(rm1[mt] + b2[ch + 8], 0.f);
        }
    }
}

// ---------------- launcher ----------------------------------------
extern "C" void kernel_launch(void* const* d_in, const int* in_sizes, int n_in,
                              void* d_out, int out_size) {
    const float* x   = (const float*)d_in[0];
    const float* pos = (const float*)d_in[1];
    // d_in[2] = batch (int32) — recomputed analytically
    const float* W1  = (const float*)d_in[3];
    const float* b1  = (const float*)d_in[4];
    const float* W2  = (const float*)d_in[5];
    const float* b2  = (const float*)d_in[6];
    float* out = (float*)d_out;

    long long off_pos   = (long long)Nn * Hd;
    long long off_batch = off_pos + (long long)Nn * 3;
    long long off_edge  = off_batch + Nn;
    long long need      = off_edge + 2LL * En;
    int write_aux = ((long long)out_size >= need) ? 1 : 0;

    knn_kernel<<<Bev*25, 256>>>(pos, x, W1, b1, out, write_aux, off_pos, off_batch, off_edge);
    mlp3_kernel<<<Nn / 4, 128>>>(W2, b2, out);
}

// round 10
// speedup vs baseline: 1.1206x; 1.1206x over previous
#include <cuda_runtime.h>
#include <cuda_fp16.h>
#include <cstdint>
#include <cfloat>
#include <math_constants.h>

#define Bev 128
#define Pn  200
#define Kn  60
#define Hd  64
#define Nn  (Bev*Pn)          // 25600
#define En  (Nn*Kn)           // 1,536,000

// ---------------- scratch (no cudaMalloc allowed) ----------------
__device__ __align__(16) float g_u[Nn*Hd];   // u = x@W1[:4] + pos@W1[4:] + b1
__device__ __align__(16) float g_v[Nn*Hd];   // v = pos@W1[4:]
__device__ int   g_nbr[En];                  // sorted knn neighbor ids

// ================= helpers =========================================
__device__ __forceinline__ uint32_t smem_u32(const void* p) {
    uint32_t a;
    asm("{ .reg .u64 t; cvta.to.shared.u64 t, %1; cvt.u32.u64 %0, t; }" : "=r"(a) : "l"(p));
    return a;
}
__device__ __forceinline__ void ldsm4(uint32_t* r, uint32_t addr) {
    asm volatile("ldmatrix.sync.aligned.m8n8.x4.shared.b16 {%0,%1,%2,%3}, [%4];"
        : "=r"(r[0]), "=r"(r[1]), "=r"(r[2]), "=r"(r[3]) : "r"(addr));
}
__device__ __forceinline__ void mma16816(float* d, const uint32_t* a, const uint32_t* b) {
    asm volatile("mma.sync.aligned.m16n8k16.row.col.f32.f16.f16.f32 "
        "{%0,%1,%2,%3}, {%4,%5,%6,%7}, {%8,%9}, {%0,%1,%2,%3};"
        : "+f"(d[0]), "+f"(d[1]), "+f"(d[2]), "+f"(d[3])
        : "r"(a[0]), "r"(a[1]), "r"(a[2]), "r"(a[3]), "r"(b[0]), "r"(b[1]));
}
__device__ __forceinline__ uint32_t pkh2(__half a, __half b) {
    __half2 t = __halves2half2(a, b);
    return *reinterpret_cast<uint32_t*>(&t);
}
__device__ __forceinline__ void cpa16(uint32_t dst, const void* src) {
    asm volatile("cp.async.cg.shared.global [%0], [%1], 16;" :: "r"(dst), "l"(src));
}

// ------- kernel 1: fused uv precompute + exact knn (sorted top-60) -------
// (byte-exact round-5/round-8 version — known good, ~135us)
__global__ void __launch_bounds__(256, 1)
knn_kernel(const float* __restrict__ pos, const float* __restrict__ x,
           const float* __restrict__ W1, const float* __restrict__ b1,
           float* __restrict__ out,
           int write_aux, long long off_pos, long long off_batch, long long off_edge) {
    __shared__ float spx[Pn], spy[Pn], spz[Pn];
    __shared__ float sW1[7*64];
    __shared__ float sb1[64];
    int b = blockIdx.x;
    int tid = threadIdx.x;
    for (int t = tid; t < Pn; t += 256) {
        spx[t] = pos[(b*Pn+t)*3+0];
        spy[t] = pos[(b*Pn+t)*3+1];
        spz[t] = pos[(b*Pn+t)*3+2];
    }
    for (int t = tid; t < 7*64; t += 256) sW1[t] = W1[t];
    if (tid < 64) sb1[tid] = b1[tid];
    __syncthreads();

    for (int e = tid; e < Pn*64; e += 256) {
        int n = e >> 6, c = e & 63;
        int gn = b*Pn + n;
        float4 xv = *(const float4*)(x + (size_t)gn*4);
        float a = sb1[c];
        a = fmaf(xv.x, sW1[0*64+c], a);
        a = fmaf(xv.y, sW1[1*64+c], a);
        a = fmaf(xv.z, sW1[2*64+c], a);
        a = fmaf(xv.w, sW1[3*64+c], a);
        float vv = spx[n] * sW1[4*64+c];
        vv = fmaf(spy[n], sW1[5*64+c], vv);
        vv = fmaf(spz[n], sW1[6*64+c], vv);
        g_u[(size_t)b*Pn*64 + e] = a + vv;
        g_v[(size_t)b*Pn*64 + e] = vv;
    }

    if (tid >= Pn) return;
    int i  = tid;
    int gi = b*Pn + i;
    float pix = spx[i], piy = spy[i], piz = spz[i];

    float key[Kn];
    int   idx[Kn];
#pragma unroll
    for (int t = 0; t < Kn; t++) { key[t] = CUDART_INF_F; idx[t] = 0; }

    for (int j = 0; j < Pn; j++) {
        float dx = spx[j]-pix, dy = spy[j]-piy, dz = spz[j]-piz;
        float d2 = dx*dx; d2 = fmaf(dy,dy,d2); d2 = fmaf(dz,dz,d2);
        d2 = (j == i) ? CUDART_INF_F : d2;
        if (d2 < key[Kn-1]) {
#pragma unroll
            for (int t = Kn-1; t > 0; --t) {
                bool pa = d2 < key[t-1];
                bool pc = d2 < key[t];
                key[t] = pa ? key[t-1] : (pc ? d2 : key[t]);
                idx[t] = pa ? idx[t-1] : (pc ? j  : idx[t]);
            }
            bool p0 = d2 < key[0];
            idx[0] = p0 ? j  : idx[0];
            key[0] = p0 ? d2 : key[0];
        }
    }
#pragma unroll
    for (int t = 0; t < Kn; t++) {
        int j = idx[t];
        g_nbr[gi*Kn + t] = b*Pn + j;
        if (write_aux) {
            out[off_edge +       (long long)gi*Kn + t] = (float)(b*Pn + j);
            out[off_edge + En +  (long long)gi*Kn + t] = (float)gi;
        }
    }
    if (write_aux) {
        out[off_pos + (long long)gi*3+0] = pix;
        out[off_pos + (long long)gi*3+1] = piy;
        out[off_pos + (long long)gi*3+2] = piz;
        out[off_batch + gi] = (float)b;
    }
}

// ---------------- kernel 2: HMMA mlp + fused max-aggregate --------
// Round-8 body + register diet: aH stays resident (64 regs), aL reloaded
// from smem per mt-tile inside the loop (short live range) -> occupancy up
// without R6's full-reload L1 flood. u-gather via 2-stage cp.async as R8.
__global__ void __launch_bounds__(128)
mlp3_kernel(const float* __restrict__ W2, const float* __restrict__ b2,
            float* __restrict__ out) {
    __shared__ __align__(16) __half sW[2][64][72];    // [hi/lo][ch][k]
    __shared__ __align__(16) float  sU[4][2][8][72];  // [warp][stage][row][64+pad]
    int tid = threadIdx.x, lane = tid & 31, warp = tid >> 5;

    for (int e = tid; e < 64*64; e += 128) {
        int k = e >> 6, ch = e & 63;
        float w = W2[k*64 + ch];
        __half hi = __float2half_rn(w);
        __half lo = __float2half_rn(w - __half2float(hi));
        sW[0][ch][k] = hi;
        sW[1][ch][k] = lo;
    }
    __syncthreads();

    // ldmatrix source coords (constant all kernel)
    const int r = (lane & 7) + ((lane >> 3) & 1) * 8;
    const int c = ((lane >> 4) & 1) * 8;

    // aH resident; aL reloaded per mt-tile in the loop
    uint32_t aH[4][4][4];
#pragma unroll
    for (int mt = 0; mt < 4; mt++)
#pragma unroll
        for (int kt = 0; kt < 4; kt++)
            ldsm4(aH[mt][kt], smem_u32(&sW[0][mt*16 + r][kt*16 + c]));

    int i = blockIdx.x * 4 + warp;                    // node id
    const int cb = (lane & 3) * 2;                    // k base within k-tile
    const int mrow = lane >> 2;                       // message row in group
    const int seg  = lane & 15;                       // 16B chunk within row
    const int hi4  = lane >> 4;                       // row parity for prefetch

    int nA = g_nbr[(size_t)i*Kn + lane];
    int nB = (lane < Kn - 32) ? g_nbr[(size_t)i*Kn + 32 + lane] : 0;

    const uint32_t suBase = smem_u32(&sU[warp][0][0][0]);   // stage stride 2304B

    float2 vA[4], vB[4];
#pragma unroll
    for (int kt = 0; kt < 4; kt++) {
        vA[kt] = *(const float2*)(g_v + (size_t)i*64 + kt*16 + cb);
        vB[kt] = *(const float2*)(g_v + (size_t)i*64 + kt*16 + cb + 8);
    }

    float rm0[4], rm1[4];
#pragma unroll
    for (int mt = 0; mt < 4; mt++) { rm0[mt] = -FLT_MAX; rm1[mt] = -FLT_MAX; }

#define PREFETCH_GRP(gg, st) do {                                            \
        _Pragma("unroll")                                                    \
        for (int it = 0; it < 4; it++) {                                     \
            int rr = 2*it + hi4;                                             \
            int mm = (gg)*8 + rr;                                            \
            int jj = (mm < 32) ? __shfl_sync(0xffffffffu, nA, mm)            \
                   : (mm < Kn) ? __shfl_sync(0xffffffffu, nB, mm - 32)       \
                   : i;                                                      \
            cpa16(suBase + (st)*2304 + rr*288 + seg*16,                      \
                  (const char*)g_u + (size_t)jj*256 + seg*16);               \
        }                                                                    \
        asm volatile("cp.async.commit_group;" ::: "memory");                 \
    } while (0)

    PREFETCH_GRP(0, 0);

    for (int g = 0; g < 8; g++) {                     // 8 groups of 8 messages
        if (g < 7) {
            PREFETCH_GRP(g+1, (g+1)&1);
            asm volatile("cp.async.wait_group 1;" ::: "memory");
        } else {
            asm volatile("cp.async.wait_group 0;" ::: "memory");
        }
        __syncwarp();

        const float* su = &sU[warp][g & 1][0][0];
        uint32_t bH[4][2], bL[4][2];
#pragma unroll
        for (int kt = 0; kt < 4; kt++) {
            float2 uA = *(const float2*)(su + mrow*72 + kt*16 + cb);
            float2 uB = *(const float2*)(su + mrow*72 + kt*16 + cb + 8);
            float h0 = fmaxf(uA.x - vA[kt].x, 0.f);
            float h1 = fmaxf(uA.y - vA[kt].y, 0.f);
            float h2 = fmaxf(uB.x - vB[kt].x, 0.f);
            float h3 = fmaxf(uB.y - vB[kt].y, 0.f);
            __half q0 = __float2half_rn(h0), q1 = __float2half_rn(h1);
            __half q2 = __float2half_rn(h2), q3 = __float2half_rn(h3);
            bH[kt][0] = pkh2(q0, q1);
            bH[kt][1] = pkh2(q2, q3);
            bL[kt][0] = pkh2(__float2half_rn(h0 - __half2float(q0)),
                             __float2half_rn(h1 - __half2float(q1)));
            bL[kt][1] = pkh2(__float2half_rn(h2 - __half2float(q2)),
                             __float2half_rn(h3 - __half2float(q3)));
        }

#pragma unroll
        for (int mt = 0; mt < 4; mt++) {
            // reload aL for this tile only (short live range)
            uint32_t aLt[4][4];
#pragma unroll
            for (int kt = 0; kt < 4; kt++)
                ldsm4(aLt[kt], smem_u32(&sW[1][mt*16 + r][kt*16 + c]));

            float dh[4] = {0,0,0,0}, dl[4] = {0,0,0,0}, da[4] = {0,0,0,0};
#pragma unroll
            for (int kt = 0; kt < 4; kt++) {
                mma16816(dh, aH[mt][kt], bH[kt]);
                mma16816(dl, aH[mt][kt], bL[kt]);
                mma16816(da, aLt[kt],    bH[kt]);
            }
            float d0 = dh[0] + dl[0] + da[0];
            float d1 = dh[1] + dl[1] + da[1];
            float d2 = dh[2] + dl[2] + da[2];
            float d3 = dh[3] + dl[3] + da[3];
            rm0[mt] = fmaxf(rm0[mt], fmaxf(d0, d1));
            rm1[mt] = fmaxf(rm1[mt], fmaxf(d2, d3));
        }
        __syncwarp();   // reads of this stage done before next prefetch lands
    }

#pragma unroll
    for (int mt = 0; mt < 4; mt++) {
        rm0[mt] = fmaxf(rm0[mt], __shfl_xor_sync(0xffffffffu, rm0[mt], 1));
        rm0[mt] = fmaxf(rm0[mt], __shfl_xor_sync(0xffffffffu, rm0[mt], 2));
        rm1[mt] = fmaxf(rm1[mt], __shfl_xor_sync(0xffffffffu, rm1[mt], 1));
        rm1[mt] = fmaxf(rm1[mt], __shfl_xor_sync(0xffffffffu, rm1[mt], 2));
    }
    if ((lane & 3) == 0) {
        int rr = lane >> 2;
#pragma unroll
        for (int mt = 0; mt < 4; mt++) {
            int ch = mt*16 + rr;
            out[(size_t)i*64 + ch]     = fmaxf(rm0[mt] + b2[ch],     0.f);
            out[(size_t)i*64 + ch + 8] = fmaxf(rm1[mt] + b2[ch + 8], 0.f);
        }
    }
}

// ---------------- launcher ----------------------------------------
extern "C" void kernel_launch(void* const* d_in, const int* in_sizes, int n_in,
                              void* d_out, int out_size) {
    const float* x   = (const float*)d_in[0];
    const float* pos = (const float*)d_in[1];
    // d_in[2] = batch (int32) — recomputed analytically
    const float* W1  = (const float*)d_in[3];
    const float* b1  = (const float*)d_in[4];
    const float* W2  = (const float*)d_in[5];
    const float* b2  = (const float*)d_in[6];
    float* out = (float*)d_out;

    long long off_pos   = (long long)Nn * Hd;
    long long off_batch = off_pos + (long long)Nn * 3;
    long long off_edge  = off_batch + Nn;
    long long need      = off_edge + 2LL * En;
    int write_aux = ((long long)out_size >= need) ? 1 : 0;

    knn_kernel<<<Bev, 256>>>(pos, x, W1, b1, out, write_aux, off_pos, off_batch, off_edge);
    mlp3_kernel<<<Nn / 4, 128>>>(W2, b2, out);
}